// round 1
// baseline (speedup 1.0000x reference)
#include <cuda_runtime.h>

#define NN 8192
#define SS 4
#define EE 262144
#define HH 64
#define FF 32

// ---------------- scratch (static device allocations; no cudaMalloc) --------
__device__ __align__(256) float g_Ppart[4][NN][128];   // 16 MB: split-K partials of feat @ [W1_b0|W1_b1]
__device__ __align__(256) float g_sup1[SS][NN][HH];    //  8 MB
__device__ __align__(256) float g_x1[NN][HH];          //  2 MB (agg accumulator, pre-tanh)
__device__ __align__(256) float g_sup2[SS][NN][FF];    //  4 MB
__device__ __align__(256) float g_x2[NN][FF];          //  1 MB (agg accumulator, pre-tanh)

// ---------------- zero the two atomic accumulators ---------------------------
__global__ void zero_kernel() {
    int idx = blockIdx.x * blockDim.x + threadIdx.x;
    float4 z = make_float4(0.f, 0.f, 0.f, 0.f);
    const int n1 = NN * HH / 4;      // 131072 float4
    const int n2 = NN * FF / 4;      //  65536 float4
    if (idx < n1) {
        reinterpret_cast<float4*>(g_x1)[idx] = z;
    } else {
        int j = idx - n1;
        if (j < n2) reinterpret_cast<float4*>(g_x2)[j] = z;
    }
}

// ---------------- layer-1 GEMM: P = feat[8192,8192] @ W1cat[8192,128] --------
// 128x128 tile per CTA, BK=16, split-K=4 (grid.y), packed f32x2 FMA micro-kernel.
__global__ void __launch_bounds__(256, 2)
gemm1_kernel(const float* __restrict__ feat, const float* __restrict__ W1) {
    __shared__ float As[16][132];   // transposed A tile, padded
    __shared__ float Bs[16][128];

    const int tid     = threadIdx.x;
    const int rowBase = blockIdx.x * 128;
    const int kslice  = blockIdx.y;          // 0..3
    const int kBase   = kslice * 2048;
    const int tx      = tid & 15;            // N direction (8 cols each)
    const int ty      = tid >> 4;            // M direction (8 rows each)

    // per-thread load coordinates (2 float4 of A, 2 float4 of B per k-tile)
    int aRow[2], aCol[2], bK[2], bJ[2];
#pragma unroll
    for (int i = 0; i < 2; i++) {
        int lin = tid + i * 256;             // 0..511
        aRow[i] = lin >> 2;                  // 0..127
        aCol[i] = (lin & 3) * 4;             // 0,4,8,12
        bK[i]   = lin >> 5;                  // 0..15
        bJ[i]   = (lin & 31) * 4;            // 0..124
    }

    unsigned long long acc[8][4];
#pragma unroll
    for (int i = 0; i < 8; i++)
#pragma unroll
        for (int j = 0; j < 4; j++) acc[i][j] = 0ull;

    // prefetch k-tile 0 into registers
    float4 aR[2], bR[2];
#pragma unroll
    for (int i = 0; i < 2; i++) {
        aR[i] = *reinterpret_cast<const float4*>(
            feat + (size_t)(rowBase + aRow[i]) * NN + kBase + aCol[i]);
        int b = bJ[i] >> 6, h = bJ[i] & 63;
        bR[i] = *reinterpret_cast<const float4*>(
            W1 + ((size_t)b * NN + (size_t)(kBase + bK[i])) * 64 + h);
    }

    for (int kk = 0; kk < 2048; kk += 16) {
        // regs -> smem
#pragma unroll
        for (int i = 0; i < 2; i++) {
            As[aCol[i] + 0][aRow[i]] = aR[i].x;
            As[aCol[i] + 1][aRow[i]] = aR[i].y;
            As[aCol[i] + 2][aRow[i]] = aR[i].z;
            As[aCol[i] + 3][aRow[i]] = aR[i].w;
            *reinterpret_cast<float4*>(&Bs[bK[i]][bJ[i]]) = bR[i];
        }
        __syncthreads();

        // prefetch next k-tile (overlaps with compute below)
        if (kk + 16 < 2048) {
#pragma unroll
            for (int i = 0; i < 2; i++) {
                aR[i] = *reinterpret_cast<const float4*>(
                    feat + (size_t)(rowBase + aRow[i]) * NN + kBase + kk + 16 + aCol[i]);
                int b = bJ[i] >> 6, h = bJ[i] & 63;
                bR[i] = *reinterpret_cast<const float4*>(
                    W1 + ((size_t)b * NN + (size_t)(kBase + kk + 16 + bK[i])) * 64 + h);
            }
        }

#pragma unroll
        for (int k = 0; k < 16; k++) {
            float4 a0 = *reinterpret_cast<const float4*>(&As[k][ty * 8]);
            float4 a1 = *reinterpret_cast<const float4*>(&As[k][ty * 8 + 4]);
            float a[8] = {a0.x, a0.y, a0.z, a0.w, a1.x, a1.y, a1.z, a1.w};
            unsigned long long b2[4];
            const unsigned long long* bp =
                reinterpret_cast<const unsigned long long*>(&Bs[k][tx * 8]);
#pragma unroll
            for (int j = 0; j < 4; j++) b2[j] = bp[j];
#pragma unroll
            for (int i = 0; i < 8; i++) {
                unsigned long long a2;
                unsigned int au = __float_as_uint(a[i]);
                asm("mov.b64 %0, {%1, %1};" : "=l"(a2) : "r"(au));
#pragma unroll
                for (int j = 0; j < 4; j++)
                    asm("fma.rn.f32x2 %0, %1, %2, %0;"
                        : "+l"(acc[i][j]) : "l"(a2), "l"(b2[j]));
            }
        }
        __syncthreads();
    }

    // write split-K partial
#pragma unroll
    for (int i = 0; i < 8; i++) {
        unsigned long long* orow = reinterpret_cast<unsigned long long*>(
            &g_Ppart[kslice][rowBase + ty * 8 + i][tx * 8]);
#pragma unroll
        for (int j = 0; j < 4; j++) orow[j] = acc[i][j];
    }
}

// ---------------- combine split-K partials + basis coefficients -> sup1 ------
__global__ void sup1_kernel(const float* __restrict__ Wc1) {
    int idx = blockIdx.x * blockDim.x + threadIdx.x;   // over NN*HH
    if (idx >= NN * HH) return;
    int n = idx >> 6, h = idx & 63;
    float p0 = g_Ppart[0][n][h] + g_Ppart[1][n][h] +
               g_Ppart[2][n][h] + g_Ppart[3][n][h];
    float p1 = g_Ppart[0][n][64 + h] + g_Ppart[1][n][64 + h] +
               g_Ppart[2][n][64 + h] + g_Ppart[3][n][64 + h];
#pragma unroll
    for (int s = 0; s < 4; s++)
        g_sup1[s][n][h] = Wc1[s * 2] * p0 + Wc1[s * 2 + 1] * p1;
}

// ---------------- layer-1 aggregation: 16 threads/edge, red.v4 ---------------
__global__ void agg1_kernel(const int* __restrict__ src,
                            const int* __restrict__ dst,
                            const float* __restrict__ w) {
    int idx = blockIdx.x * blockDim.x + threadIdx.x;   // < SS*EE*16
    int h4 = idx & 15;
    int e  = idx >> 4;                                 // linear over [S,E]
    int s  = e >> 18;                                  // E = 2^18
    int es = __ldg(src + e);
    int ed = __ldg(dst + e);
    float ww = __ldg(w + e);
    const float4 v = *reinterpret_cast<const float4*>(&g_sup1[s][es][h4 * 4]);
    float x0 = v.x * ww, x1 = v.y * ww, x2 = v.z * ww, x3 = v.w * ww;
    float* o = &g_x1[ed][h4 * 4];
    asm volatile("red.global.add.v4.f32 [%0], {%1, %2, %3, %4};"
                 :: "l"(o), "f"(x0), "f"(x1), "f"(x2), "f"(x3) : "memory");
}

// ---------------- layer 2 dense: sup2[s] = tanh(x1) @ (Wc2[s,.]·W2) ----------
__global__ void sup2_kernel(const float* __restrict__ W2,
                            const float* __restrict__ Wc2) {
    __shared__ float V2s[4][64][32];   // 32 KB
    __shared__ float x1s[64][64];      // 16 KB
    int tid   = threadIdx.x;
    int node0 = blockIdx.x * 64;

    // build V2[s] = Wc2[s,0]*W2[0] + Wc2[s,1]*W2[1]
    for (int i = tid; i < 4 * 64 * 32; i += 256) {
        int s = i >> 11, k = (i >> 5) & 63, f = i & 31;
        V2s[s][k][f] = Wc2[2 * s] * W2[k * 32 + f] +
                       Wc2[2 * s + 1] * W2[64 * 32 + k * 32 + f];
    }
    // load x1 tile with tanh applied (layer-1 activation)
    for (int i = tid; i < 64 * 64; i += 256) {
        int n = i >> 6, k = i & 63;
        x1s[n][k] = tanhf(g_x1[node0 + n][k]);
    }
    __syncthreads();

    int q = tid & 3;        // relation
    int n = tid >> 2;       // local node 0..63
    float acc[32];
#pragma unroll
    for (int f = 0; f < 32; f++) acc[f] = 0.f;
#pragma unroll 4
    for (int k = 0; k < 64; k++) {
        float a = x1s[n][k];
#pragma unroll
        for (int f = 0; f < 32; f++) acc[f] += a * V2s[q][k][f];
    }
    float4* orow = reinterpret_cast<float4*>(&g_sup2[q][node0 + n][0]);
#pragma unroll
    for (int f4 = 0; f4 < 8; f4++)
        orow[f4] = make_float4(acc[f4 * 4], acc[f4 * 4 + 1],
                               acc[f4 * 4 + 2], acc[f4 * 4 + 3]);
}

// ---------------- layer-2 aggregation: 8 threads/edge, red.v4 ----------------
__global__ void agg2_kernel(const int* __restrict__ src,
                            const int* __restrict__ dst,
                            const float* __restrict__ w) {
    int idx = blockIdx.x * blockDim.x + threadIdx.x;   // < SS*EE*8
    int h4 = idx & 7;
    int e  = idx >> 3;
    int s  = e >> 18;
    int es = __ldg(src + e);
    int ed = __ldg(dst + e);
    float ww = __ldg(w + e);
    const float4 v = *reinterpret_cast<const float4*>(&g_sup2[s][es][h4 * 4]);
    float x0 = v.x * ww, x1 = v.y * ww, x2 = v.z * ww, x3 = v.w * ww;
    float* o = &g_x2[ed][h4 * 4];
    asm volatile("red.global.add.v4.f32 [%0], {%1, %2, %3, %4};"
                 :: "l"(o), "f"(x0), "f"(x1), "f"(x2), "f"(x3) : "memory");
}

// ---------------- classifier: out = tanh(x2) @ Wclf + bclf -------------------
__global__ void clf_kernel(const float* __restrict__ Wclf,
                           const float* __restrict__ bclf,
                           float* __restrict__ out) {
    int n = blockIdx.x * blockDim.x + threadIdx.x;
    if (n >= NN) return;
    float acc0 = bclf[0], acc1 = bclf[1];
#pragma unroll
    for (int f = 0; f < 32; f++) {
        float x = tanhf(g_x2[n][f]);
        acc0 += x * Wclf[f * 2 + 0];
        acc1 += x * Wclf[f * 2 + 1];
    }
    out[n * 2 + 0] = acc0;
    out[n * 2 + 1] = acc1;
}

// -----------------------------------------------------------------------------
extern "C" void kernel_launch(void* const* d_in, const int* in_sizes, int n_in,
                              void* d_out, int out_size) {
    const float* feat   = (const float*)d_in[0];
    const float* edge_w = (const float*)d_in[1];
    const float* W1     = (const float*)d_in[2];
    const float* Wc1    = (const float*)d_in[3];
    const float* W2     = (const float*)d_in[4];
    const float* Wc2    = (const float*)d_in[5];
    const float* Wclf   = (const float*)d_in[6];
    const float* bclf   = (const float*)d_in[7];
    const int*   esrc   = (const int*)d_in[8];
    const int*   edst   = (const int*)d_in[9];
    float* out = (float*)d_out;

    zero_kernel<<<768, 256>>>();
    gemm1_kernel<<<dim3(64, 4), 256>>>(feat, W1);
    sup1_kernel<<<(NN * HH) / 256, 256>>>(Wc1);
    agg1_kernel<<<(SS * EE * 16) / 256, 256>>>(esrc, edst, edge_w);
    sup2_kernel<<<NN / 64, 256>>>(W2, Wc2);
    agg2_kernel<<<(SS * EE * 8) / 256, 256>>>(esrc, edst, edge_w);
    clf_kernel<<<NN / 256, 256>>>(Wclf, bclf, out);
}

// round 2
// speedup vs baseline: 1.1860x; 1.1860x over previous
#include <cuda_runtime.h>
#include <cstdint>

#define NN 8192
#define SS 4
#define EE 262144
#define HH 64
#define FF 32

// ---------------- scratch (static device allocations; no cudaMalloc) --------
__device__ __align__(256) float g_Ppart[4][NN][128];   // 16 MB: split-K partials of feat @ [W1_b0|W1_b1]
__device__ __align__(256) float g_sup1[SS][NN][HH];    //  8 MB
__device__ __align__(256) float g_x1[NN][HH];          //  2 MB (agg accumulator, pre-tanh)
__device__ __align__(256) float g_sup2[SS][NN][FF];    //  4 MB
__device__ __align__(256) float g_x2[NN][FF];          //  1 MB (agg accumulator, pre-tanh)

// ---------------- zero the two atomic accumulators ---------------------------
__global__ void zero_kernel() {
    int idx = blockIdx.x * blockDim.x + threadIdx.x;
    float4 z = make_float4(0.f, 0.f, 0.f, 0.f);
    const int n1 = NN * HH / 4;      // 131072 float4
    const int n2 = NN * FF / 4;      //  65536 float4
    if (idx < n1) {
        reinterpret_cast<float4*>(g_x1)[idx] = z;
    } else {
        int j = idx - n1;
        if (j < n2) reinterpret_cast<float4*>(g_x2)[j] = z;
    }
}

// ---------------- tf32 helpers ------------------------------------------------
__device__ __forceinline__ void split_tf32(float x, uint32_t& hi, uint32_t& lo) {
    asm("cvt.rna.tf32.f32 %0, %1;" : "=r"(hi) : "f"(x));
    float r = x - __uint_as_float(hi);
    asm("cvt.rna.tf32.f32 %0, %1;" : "=r"(lo) : "f"(r));
}

__device__ __forceinline__ void mma_tf32(float* c, const uint32_t* a, const uint32_t* b) {
    asm volatile(
        "mma.sync.aligned.m16n8k8.row.col.f32.tf32.tf32.f32 "
        "{%0,%1,%2,%3}, {%4,%5,%6,%7}, {%8,%9}, {%0,%1,%2,%3};"
        : "+f"(c[0]), "+f"(c[1]), "+f"(c[2]), "+f"(c[3])
        : "r"(a[0]), "r"(a[1]), "r"(a[2]), "r"(a[3]),
          "r"(b[0]), "r"(b[1]));
}

// ---------------- layer-1 GEMM: P = feat[8192,8192] @ W1cat[8192,128] --------
// tf32x3 tensor-core GEMM. 128x128 CTA tile, BK=32, split-K=4 (grid.y).
// 8 warps as 4(m) x 2(n); warp tile 32x64; m16n8k8 tiles 2x8 per warp.
__global__ void __launch_bounds__(256, 1)
gemm1_tc(const float* __restrict__ feat, const float* __restrict__ W1) {
    __shared__ float As[128][36];   // A tile [m][k], padded
    __shared__ float Bs[32][132];   // B tile [k][n], padded

    const int tid  = threadIdx.x;
    const int lane = tid & 31;
    const int warp = tid >> 5;
    const int wm   = warp & 3;       // 0..3 -> rows wm*32
    const int wn   = warp >> 2;      // 0..1 -> cols wn*64
    const int g    = lane >> 2;      // group id 0..7
    const int tig  = lane & 3;       // thread-in-group 0..3

    const int rowBase = blockIdx.x * 128;
    const int kBase   = blockIdx.y * 2048;

    float c[2][8][4];
#pragma unroll
    for (int i = 0; i < 2; i++)
#pragma unroll
        for (int j = 0; j < 8; j++)
#pragma unroll
            for (int q = 0; q < 4; q++) c[i][j][q] = 0.f;

    // per-thread gmem load coords: 4 float4 of A + 4 float4 of B per k-tile
    // A tile: 128 rows x 32 cols = 1024 float4; f = tid + i*256
    // B tile:  32 rows(k) x 128 cols(n) = 1024 float4
    float4 aR[4], bR[4];

    auto ldA = [&](int kk, int i) {
        int f = tid + (i << 8);
        int r = f >> 3, cc = (f & 7) << 2;
        return *reinterpret_cast<const float4*>(
            feat + (size_t)(rowBase + r) * NN + kBase + kk + cc);
    };
    auto ldB = [&](int kk, int i) {
        int f = tid + (i << 8);
        int k = f >> 5, n = (f & 31) << 2;
        int b = n >> 6, h = n & 63;
        return *reinterpret_cast<const float4*>(
            W1 + ((size_t)b * NN + (size_t)(kBase + kk + k)) * 64 + h);
    };

#pragma unroll
    for (int i = 0; i < 4; i++) { aR[i] = ldA(0, i); bR[i] = ldB(0, i); }

    for (int kk = 0; kk < 2048; kk += 32) {
        // regs -> smem
#pragma unroll
        for (int i = 0; i < 4; i++) {
            int f = tid + (i << 8);
            int r = f >> 3, cc = (f & 7) << 2;
            *reinterpret_cast<float4*>(&As[r][cc]) = aR[i];
            int k = f >> 5, n = (f & 31) << 2;
            *reinterpret_cast<float4*>(&Bs[k][n]) = bR[i];
        }
        __syncthreads();

        // prefetch next k-tile
        if (kk + 32 < 2048) {
#pragma unroll
            for (int i = 0; i < 4; i++) {
                aR[i] = ldA(kk + 32, i);
                bR[i] = ldB(kk + 32, i);
            }
        }

#pragma unroll
        for (int k8 = 0; k8 < 4; k8++) {
            const int kc = k8 * 8;
            uint32_t Ah[2][4], Al[2][4], Bh[8][2], Bl[8][2];
#pragma unroll
            for (int i = 0; i < 2; i++) {
                const int r0 = wm * 32 + i * 16;
                float x0 = As[r0 + g][kc + tig];
                float x1 = As[r0 + 8 + g][kc + tig];
                float x2 = As[r0 + g][kc + tig + 4];
                float x3 = As[r0 + 8 + g][kc + tig + 4];
                split_tf32(x0, Ah[i][0], Al[i][0]);
                split_tf32(x1, Ah[i][1], Al[i][1]);
                split_tf32(x2, Ah[i][2], Al[i][2]);
                split_tf32(x3, Ah[i][3], Al[i][3]);
            }
#pragma unroll
            for (int j = 0; j < 8; j++) {
                const int cb = wn * 64 + j * 8 + g;
                float y0 = Bs[kc + tig][cb];
                float y1 = Bs[kc + tig + 4][cb];
                split_tf32(y0, Bh[j][0], Bl[j][0]);
                split_tf32(y1, Bh[j][1], Bl[j][1]);
            }
#pragma unroll
            for (int i = 0; i < 2; i++)
#pragma unroll
                for (int j = 0; j < 8; j++) {
                    mma_tf32(c[i][j], Al[i], Bh[j]);   // low-order first
                    mma_tf32(c[i][j], Ah[i], Bl[j]);
                    mma_tf32(c[i][j], Ah[i], Bh[j]);
                }
        }
        __syncthreads();
    }

    // write split-K partial
    const int kslice = blockIdx.y;
#pragma unroll
    for (int i = 0; i < 2; i++) {
        const int row = rowBase + wm * 32 + i * 16 + g;
#pragma unroll
        for (int j = 0; j < 8; j++) {
            const int col = wn * 64 + j * 8 + 2 * tig;
            *reinterpret_cast<float2*>(&g_Ppart[kslice][row][col]) =
                make_float2(c[i][j][0], c[i][j][1]);
            *reinterpret_cast<float2*>(&g_Ppart[kslice][row + 8][col]) =
                make_float2(c[i][j][2], c[i][j][3]);
        }
    }
}

// ---------------- combine split-K partials + basis coefficients -> sup1 ------
__global__ void sup1_kernel(const float* __restrict__ Wc1) {
    int idx = blockIdx.x * blockDim.x + threadIdx.x;   // over NN*HH
    if (idx >= NN * HH) return;
    int n = idx >> 6, h = idx & 63;
    float p0 = g_Ppart[0][n][h] + g_Ppart[1][n][h] +
               g_Ppart[2][n][h] + g_Ppart[3][n][h];
    float p1 = g_Ppart[0][n][64 + h] + g_Ppart[1][n][64 + h] +
               g_Ppart[2][n][64 + h] + g_Ppart[3][n][64 + h];
#pragma unroll
    for (int s = 0; s < 4; s++)
        g_sup1[s][n][h] = Wc1[s * 2] * p0 + Wc1[s * 2 + 1] * p1;
}

// ---------------- layer-1 aggregation: 16 threads/edge, red.v4 ---------------
__global__ void agg1_kernel(const int* __restrict__ src,
                            const int* __restrict__ dst,
                            const float* __restrict__ w) {
    int idx = blockIdx.x * blockDim.x + threadIdx.x;   // < SS*EE*16
    int h4 = idx & 15;
    int e  = idx >> 4;                                 // linear over [S,E]
    int s  = e >> 18;                                  // E = 2^18
    int es = __ldg(src + e);
    int ed = __ldg(dst + e);
    float ww = __ldg(w + e);
    const float4 v = *reinterpret_cast<const float4*>(&g_sup1[s][es][h4 * 4]);
    float x0 = v.x * ww, x1 = v.y * ww, x2 = v.z * ww, x3 = v.w * ww;
    float* o = &g_x1[ed][h4 * 4];
    asm volatile("red.global.add.v4.f32 [%0], {%1, %2, %3, %4};"
                 :: "l"(o), "f"(x0), "f"(x1), "f"(x2), "f"(x3) : "memory");
}

// ---------------- layer 2 dense: sup2[s] = tanh(x1) @ (Wc2[s,.]·W2) ----------
__global__ void sup2_kernel(const float* __restrict__ W2,
                            const float* __restrict__ Wc2) {
    __shared__ float V2s[4][64][32];   // 32 KB
    __shared__ float x1s[64][64];      // 16 KB
    int tid   = threadIdx.x;
    int node0 = blockIdx.x * 64;

    // build V2[s] = Wc2[s,0]*W2[0] + Wc2[s,1]*W2[1]
    for (int i = tid; i < 4 * 64 * 32; i += 256) {
        int s = i >> 11, k = (i >> 5) & 63, f = i & 31;
        V2s[s][k][f] = Wc2[2 * s] * W2[k * 32 + f] +
                       Wc2[2 * s + 1] * W2[64 * 32 + k * 32 + f];
    }
    // load x1 tile with tanh applied (layer-1 activation)
    for (int i = tid; i < 64 * 64; i += 256) {
        int n = i >> 6, k = i & 63;
        x1s[n][k] = tanhf(g_x1[node0 + n][k]);
    }
    __syncthreads();

    int q = tid & 3;        // relation
    int n = tid >> 2;       // local node 0..63
    float acc[32];
#pragma unroll
    for (int f = 0; f < 32; f++) acc[f] = 0.f;
#pragma unroll 4
    for (int k = 0; k < 64; k++) {
        float a = x1s[n][k];
#pragma unroll
        for (int f = 0; f < 32; f++) acc[f] += a * V2s[q][k][f];
    }
    float4* orow = reinterpret_cast<float4*>(&g_sup2[q][node0 + n][0]);
#pragma unroll
    for (int f4 = 0; f4 < 8; f4++)
        orow[f4] = make_float4(acc[f4 * 4], acc[f4 * 4 + 1],
                               acc[f4 * 4 + 2], acc[f4 * 4 + 3]);
}

// ---------------- layer-2 aggregation: 8 threads/edge, red.v4 ----------------
__global__ void agg2_kernel(const int* __restrict__ src,
                            const int* __restrict__ dst,
                            const float* __restrict__ w) {
    int idx = blockIdx.x * blockDim.x + threadIdx.x;   // < SS*EE*8
    int h4 = idx & 7;
    int e  = idx >> 3;
    int s  = e >> 18;
    int es = __ldg(src + e);
    int ed = __ldg(dst + e);
    float ww = __ldg(w + e);
    const float4 v = *reinterpret_cast<const float4*>(&g_sup2[s][es][h4 * 4]);
    float x0 = v.x * ww, x1 = v.y * ww, x2 = v.z * ww, x3 = v.w * ww;
    float* o = &g_x2[ed][h4 * 4];
    asm volatile("red.global.add.v4.f32 [%0], {%1, %2, %3, %4};"
                 :: "l"(o), "f"(x0), "f"(x1), "f"(x2), "f"(x3) : "memory");
}

// ---------------- classifier: out = tanh(x2) @ Wclf + bclf -------------------
__global__ void clf_kernel(const float* __restrict__ Wclf,
                           const float* __restrict__ bclf,
                           float* __restrict__ out) {
    int n = blockIdx.x * blockDim.x + threadIdx.x;
    if (n >= NN) return;
    float acc0 = bclf[0], acc1 = bclf[1];
#pragma unroll
    for (int f = 0; f < 32; f++) {
        float x = tanhf(g_x2[n][f]);
        acc0 += x * Wclf[f * 2 + 0];
        acc1 += x * Wclf[f * 2 + 1];
    }
    out[n * 2 + 0] = acc0;
    out[n * 2 + 1] = acc1;
}

// -----------------------------------------------------------------------------
extern "C" void kernel_launch(void* const* d_in, const int* in_sizes, int n_in,
                              void* d_out, int out_size) {
    const float* feat   = (const float*)d_in[0];
    const float* edge_w = (const float*)d_in[1];
    const float* W1     = (const float*)d_in[2];
    const float* Wc1    = (const float*)d_in[3];
    const float* W2     = (const float*)d_in[4];
    const float* Wc2    = (const float*)d_in[5];
    const float* Wclf   = (const float*)d_in[6];
    const float* bclf   = (const float*)d_in[7];
    const int*   esrc   = (const int*)d_in[8];
    const int*   edst   = (const int*)d_in[9];
    float* out = (float*)d_out;

    zero_kernel<<<768, 256>>>();
    gemm1_tc<<<dim3(64, 4), 256>>>(feat, W1);
    sup1_kernel<<<(NN * HH) / 256, 256>>>(Wc1);
    agg1_kernel<<<(SS * EE * 16) / 256, 256>>>(esrc, edst, edge_w);
    sup2_kernel<<<NN / 64, 256>>>(W2, Wc2);
    agg2_kernel<<<(SS * EE * 8) / 256, 256>>>(esrc, edst, edge_w);
    clf_kernel<<<NN / 256, 256>>>(Wclf, bclf, out);
}

// round 4
// speedup vs baseline: 1.6748x; 1.4121x over previous
#include <cuda_runtime.h>
#include <cuda_fp16.h>
#include <cstdint>

#define NN 8192
#define SS 4
#define EE 262144
#define HH 64
#define FF 32

// ---------------- scratch (static device allocations; no cudaMalloc) --------
__device__ __align__(256) float  g_Ppart[4][NN][128];  // 16 MB split-K partials
__device__ __align__(256) __half g_Bh[128][NN];        // 2 MB: W1cat^T hi plane (fp16)
__device__ __align__(256) __half g_Bl[128][NN];        // 2 MB: W1cat^T lo plane (fp16)
__device__ __align__(256) float  g_sup1[SS][NN][HH];   // 8 MB
__device__ __align__(256) float  g_x1[NN][HH];         // 2 MB
__device__ __align__(256) float  g_sup2[SS][NN][FF];   // 4 MB
__device__ __align__(256) float  g_x2[NN][FF];         // 1 MB

// ---------------- zero the two atomic accumulators ---------------------------
__global__ void zero_kernel() {
    int idx = blockIdx.x * blockDim.x + threadIdx.x;
    float4 z = make_float4(0.f, 0.f, 0.f, 0.f);
    const int n1 = NN * HH / 4;
    const int n2 = NN * FF / 4;
    if (idx < n1) {
        reinterpret_cast<float4*>(g_x1)[idx] = z;
    } else {
        int j = idx - n1;
        if (j < n2) reinterpret_cast<float4*>(g_x2)[j] = z;
    }
}

// ---------------- fp16 split helpers ------------------------------------------
__device__ __forceinline__ void split_h(float x, __half& hi, __half& lo) {
    hi = __float2half_rn(x);
    lo = __float2half_rn(x - __half2float(hi));
}

__device__ __forceinline__ void mma_f16(float* c, const uint32_t* a, const uint32_t* b) {
    asm volatile(
        "mma.sync.aligned.m16n8k16.row.col.f32.f16.f16.f32 "
        "{%0,%1,%2,%3}, {%4,%5,%6,%7}, {%8,%9}, {%0,%1,%2,%3};"
        : "+f"(c[0]), "+f"(c[1]), "+f"(c[2]), "+f"(c[3])
        : "r"(a[0]), "r"(a[1]), "r"(a[2]), "r"(a[3]),
          "r"(b[0]), "r"(b[1]));
}

// ---------------- pre-split B = W1cat^T into fp16 hi/lo planes ----------------
// g_Bh[n][k], g_Bl[n][k]; n = b*64 + h, from W1[b][k][h].
__global__ void bsplit_kernel(const float* __restrict__ W1) {
    int lin = blockIdx.x * 256 + threadIdx.x;   // 128*8192/4 threads
    int n = lin >> 11;
    int k = (lin & 2047) << 2;
    int b = n >> 6, h = n & 63;
    __half hh[4], ll[4];
#pragma unroll
    for (int q = 0; q < 4; q++) {
        float v = W1[((size_t)b * NN + k + q) * 64 + h];
        split_h(v, hh[q], ll[q]);
    }
    *reinterpret_cast<half2*>(&g_Bh[n][k])     = __halves2half2(hh[0], hh[1]);
    *reinterpret_cast<half2*>(&g_Bh[n][k + 2]) = __halves2half2(hh[2], hh[3]);
    *reinterpret_cast<half2*>(&g_Bl[n][k])     = __halves2half2(ll[0], ll[1]);
    *reinterpret_cast<half2*>(&g_Bl[n][k + 2]) = __halves2half2(ll[2], ll[3]);
}

// ---------------- layer-1 GEMM: P = feat[8192,8192] @ W1cat[8192,128] --------
// fp16x3 (hi/lo split) tensor-core GEMM via mma.sync.m16n8k16.
// 128x128 CTA tile, BK=32, split-K=4 (grid.y). 8 warps = 4(m) x 2(n);
// warp tile 32x64 -> 2x8 m16n8 tiles, 2 k16 steps per k-tile, 3 terms each.
__global__ void __launch_bounds__(256, 1)
gemm1_h3(const float* __restrict__ feat) {
    __shared__ __half Ah[128][40];   // A hi, [m][k], stride 40 halves (conflict-free)
    __shared__ __half Al[128][40];   // A lo
    __shared__ __half Bs_h[128][40]; // B hi, [n][k]
    __shared__ __half Bs_l[128][40]; // B lo

    const int tid  = threadIdx.x;
    const int lane = tid & 31;
    const int warp = tid >> 5;
    const int wm   = warp & 3;       // m slice: rows wm*32
    const int wn   = warp >> 2;      // n slice: cols wn*64
    const int g    = lane >> 2;      // 0..7
    const int t    = lane & 3;       // 0..3

    const int rowBase = blockIdx.x * 128;
    const int kBase   = blockIdx.y * 2048;

    float c[2][8][4];
#pragma unroll
    for (int i = 0; i < 2; i++)
#pragma unroll
        for (int j = 0; j < 8; j++)
#pragma unroll
            for (int q = 0; q < 4; q++) c[i][j][q] = 0.f;

    // prefetch registers
    float4 aR[4];        // A: 128x32 fp32 = 1024 float4, 4 per thread
    uint4  bHr[2], bLr[2]; // B: 128x32 halves per plane = 512 uint4, 2 per thread

    auto ldA = [&](int kk, int i) {
        int f = tid + (i << 8);
        int r = f >> 3, cc = (f & 7) << 2;
        return *reinterpret_cast<const float4*>(
            feat + (size_t)(rowBase + r) * NN + kBase + kk + cc);
    };
    auto ldBh = [&](int kk, int i) {
        int f = tid + (i << 8);
        int n = f >> 2, seg = (f & 3) << 3;
        return *reinterpret_cast<const uint4*>(&g_Bh[n][kBase + kk + seg]);
    };
    auto ldBl = [&](int kk, int i) {
        int f = tid + (i << 8);
        int n = f >> 2, seg = (f & 3) << 3;
        return *reinterpret_cast<const uint4*>(&g_Bl[n][kBase + kk + seg]);
    };

#pragma unroll
    for (int i = 0; i < 4; i++) aR[i] = ldA(0, i);
#pragma unroll
    for (int i = 0; i < 2; i++) { bHr[i] = ldBh(0, i); bLr[i] = ldBl(0, i); }

    for (int kk = 0; kk < 2048; kk += 32) {
        // regs -> smem (A split on the fly)
#pragma unroll
        for (int i = 0; i < 4; i++) {
            int f = tid + (i << 8);
            int r = f >> 3, cc = (f & 7) << 2;
            __half hx, lx, hy, ly, hz, lz, hw, lw;
            split_h(aR[i].x, hx, lx);
            split_h(aR[i].y, hy, ly);
            split_h(aR[i].z, hz, lz);
            split_h(aR[i].w, hw, lw);
            *reinterpret_cast<half2*>(&Ah[r][cc])     = __halves2half2(hx, hy);
            *reinterpret_cast<half2*>(&Ah[r][cc + 2]) = __halves2half2(hz, hw);
            *reinterpret_cast<half2*>(&Al[r][cc])     = __halves2half2(lx, ly);
            *reinterpret_cast<half2*>(&Al[r][cc + 2]) = __halves2half2(lz, lw);
        }
#pragma unroll
        for (int i = 0; i < 2; i++) {
            int f = tid + (i << 8);
            int n = f >> 2, seg = (f & 3) << 3;
            *reinterpret_cast<uint4*>(&Bs_h[n][seg]) = bHr[i];
            *reinterpret_cast<uint4*>(&Bs_l[n][seg]) = bLr[i];
        }
        __syncthreads();

        // prefetch next k-tile
        if (kk + 32 < 2048) {
#pragma unroll
            for (int i = 0; i < 4; i++) aR[i] = ldA(kk + 32, i);
#pragma unroll
            for (int i = 0; i < 2; i++) {
                bHr[i] = ldBh(kk + 32, i);
                bLr[i] = ldBl(kk + 32, i);
            }
        }

#pragma unroll
        for (int kc = 0; kc < 32; kc += 16) {
            uint32_t Ahf[2][4], Alf[2][4], Bhf[8][2], Blf[8][2];
#pragma unroll
            for (int i = 0; i < 2; i++) {
                const int r0 = wm * 32 + i * 16;
                Ahf[i][0] = *reinterpret_cast<const uint32_t*>(&Ah[r0 + g][kc + 2 * t]);
                Ahf[i][1] = *reinterpret_cast<const uint32_t*>(&Ah[r0 + 8 + g][kc + 2 * t]);
                Ahf[i][2] = *reinterpret_cast<const uint32_t*>(&Ah[r0 + g][kc + 8 + 2 * t]);
                Ahf[i][3] = *reinterpret_cast<const uint32_t*>(&Ah[r0 + 8 + g][kc + 8 + 2 * t]);
                Alf[i][0] = *reinterpret_cast<const uint32_t*>(&Al[r0 + g][kc + 2 * t]);
                Alf[i][1] = *reinterpret_cast<const uint32_t*>(&Al[r0 + 8 + g][kc + 2 * t]);
                Alf[i][2] = *reinterpret_cast<const uint32_t*>(&Al[r0 + g][kc + 8 + 2 * t]);
                Alf[i][3] = *reinterpret_cast<const uint32_t*>(&Al[r0 + 8 + g][kc + 8 + 2 * t]);
            }
#pragma unroll
            for (int j = 0; j < 8; j++) {
                const int c0 = wn * 64 + j * 8 + g;
                Bhf[j][0] = *reinterpret_cast<const uint32_t*>(&Bs_h[c0][kc + 2 * t]);
                Bhf[j][1] = *reinterpret_cast<const uint32_t*>(&Bs_h[c0][kc + 8 + 2 * t]);
                Blf[j][0] = *reinterpret_cast<const uint32_t*>(&Bs_l[c0][kc + 2 * t]);
                Blf[j][1] = *reinterpret_cast<const uint32_t*>(&Bs_l[c0][kc + 8 + 2 * t]);
            }
#pragma unroll
            for (int i = 0; i < 2; i++)
#pragma unroll
                for (int j = 0; j < 8; j++) {
                    mma_f16(c[i][j], Alf[i], Bhf[j]);   // low-order first
                    mma_f16(c[i][j], Ahf[i], Blf[j]);
                    mma_f16(c[i][j], Ahf[i], Bhf[j]);
                }
        }
        __syncthreads();
    }

    // write split-K partial
    const int kslice = blockIdx.y;
#pragma unroll
    for (int i = 0; i < 2; i++) {
        const int row = rowBase + wm * 32 + i * 16 + g;
#pragma unroll
        for (int j = 0; j < 8; j++) {
            const int col = wn * 64 + j * 8 + 2 * t;
            *reinterpret_cast<float2*>(&g_Ppart[kslice][row][col]) =
                make_float2(c[i][j][0], c[i][j][1]);
            *reinterpret_cast<float2*>(&g_Ppart[kslice][row + 8][col]) =
                make_float2(c[i][j][2], c[i][j][3]);
        }
    }
}

// ---------------- combine split-K partials + basis coefficients -> sup1 ------
__global__ void sup1_kernel(const float* __restrict__ Wc1) {
    int idx = blockIdx.x * blockDim.x + threadIdx.x;
    if (idx >= NN * HH) return;
    int n = idx >> 6, h = idx & 63;
    float p0 = g_Ppart[0][n][h] + g_Ppart[1][n][h] +
               g_Ppart[2][n][h] + g_Ppart[3][n][h];
    float p1 = g_Ppart[0][n][64 + h] + g_Ppart[1][n][64 + h] +
               g_Ppart[2][n][64 + h] + g_Ppart[3][n][64 + h];
#pragma unroll
    for (int s = 0; s < 4; s++)
        g_sup1[s][n][h] = Wc1[s * 2] * p0 + Wc1[s * 2 + 1] * p1;
}

// ---------------- layer-1 aggregation: 16 threads/edge, red.v4 ---------------
__global__ void agg1_kernel(const int* __restrict__ src,
                            const int* __restrict__ dst,
                            const float* __restrict__ w) {
    int idx = blockIdx.x * blockDim.x + threadIdx.x;
    int h4 = idx & 15;
    int e  = idx >> 4;
    int s  = e >> 18;
    int es = __ldg(src + e);
    int ed = __ldg(dst + e);
    float ww = __ldg(w + e);
    const float4 v = *reinterpret_cast<const float4*>(&g_sup1[s][es][h4 * 4]);
    float x0 = v.x * ww, x1 = v.y * ww, x2 = v.z * ww, x3 = v.w * ww;
    float* o = &g_x1[ed][h4 * 4];
    asm volatile("red.global.add.v4.f32 [%0], {%1, %2, %3, %4};"
                 :: "l"(o), "f"(x0), "f"(x1), "f"(x2), "f"(x3) : "memory");
}

// ---------------- layer 2 dense: sup2[s] = tanh(x1) @ (Wc2[s,.]·W2) ----------
__global__ void sup2_kernel(const float* __restrict__ W2,
                            const float* __restrict__ Wc2) {
    __shared__ float V2s[4][64][32];
    __shared__ float x1s[64][64];
    int tid   = threadIdx.x;
    int node0 = blockIdx.x * 64;

    for (int i = tid; i < 4 * 64 * 32; i += 256) {
        int s = i >> 11, k = (i >> 5) & 63, f = i & 31;
        V2s[s][k][f] = Wc2[2 * s] * W2[k * 32 + f] +
                       Wc2[2 * s + 1] * W2[64 * 32 + k * 32 + f];
    }
    for (int i = tid; i < 64 * 64; i += 256) {
        int n = i >> 6, k = i & 63;
        x1s[n][k] = tanhf(g_x1[node0 + n][k]);
    }
    __syncthreads();

    int q = tid & 3;
    int n = tid >> 2;
    float acc[32];
#pragma unroll
    for (int f = 0; f < 32; f++) acc[f] = 0.f;
#pragma unroll 4
    for (int k = 0; k < 64; k++) {
        float a = x1s[n][k];
#pragma unroll
        for (int f = 0; f < 32; f++) acc[f] += a * V2s[q][k][f];
    }
    float4* orow = reinterpret_cast<float4*>(&g_sup2[q][node0 + n][0]);
#pragma unroll
    for (int f4 = 0; f4 < 8; f4++)
        orow[f4] = make_float4(acc[f4 * 4], acc[f4 * 4 + 1],
                               acc[f4 * 4 + 2], acc[f4 * 4 + 3]);
}

// ---------------- layer-2 aggregation: 8 threads/edge, red.v4 ----------------
__global__ void agg2_kernel(const int* __restrict__ src,
                            const int* __restrict__ dst,
                            const float* __restrict__ w) {
    int idx = blockIdx.x * blockDim.x + threadIdx.x;
    int h4 = idx & 7;
    int e  = idx >> 3;
    int s  = e >> 18;
    int es = __ldg(src + e);
    int ed = __ldg(dst + e);
    float ww = __ldg(w + e);
    const float4 v = *reinterpret_cast<const float4*>(&g_sup2[s][es][h4 * 4]);
    float x0 = v.x * ww, x1 = v.y * ww, x2 = v.z * ww, x3 = v.w * ww;
    float* o = &g_x2[ed][h4 * 4];
    asm volatile("red.global.add.v4.f32 [%0], {%1, %2, %3, %4};"
                 :: "l"(o), "f"(x0), "f"(x1), "f"(x2), "f"(x3) : "memory");
}

// ---------------- classifier: out = tanh(x2) @ Wclf + bclf -------------------
__global__ void clf_kernel(const float* __restrict__ Wclf,
                           const float* __restrict__ bclf,
                           float* __restrict__ out) {
    int n = blockIdx.x * blockDim.x + threadIdx.x;
    if (n >= NN) return;
    float acc0 = bclf[0], acc1 = bclf[1];
#pragma unroll
    for (int f = 0; f < 32; f++) {
        float x = tanhf(g_x2[n][f]);
        acc0 += x * Wclf[f * 2 + 0];
        acc1 += x * Wclf[f * 2 + 1];
    }
    out[n * 2 + 0] = acc0;
    out[n * 2 + 1] = acc1;
}

// -----------------------------------------------------------------------------
extern "C" void kernel_launch(void* const* d_in, const int* in_sizes, int n_in,
                              void* d_out, int out_size) {
    const float* feat   = (const float*)d_in[0];
    const float* edge_w = (const float*)d_in[1];
    const float* W1     = (const float*)d_in[2];
    const float* Wc1    = (const float*)d_in[3];
    const float* W2     = (const float*)d_in[4];
    const float* Wc2    = (const float*)d_in[5];
    const float* Wclf   = (const float*)d_in[6];
    const float* bclf   = (const float*)d_in[7];
    const int*   esrc   = (const int*)d_in[8];
    const int*   edst   = (const int*)d_in[9];
    float* out = (float*)d_out;

    zero_kernel<<<768, 256>>>();
    bsplit_kernel<<<1024, 256>>>(W1);
    gemm1_h3<<<dim3(64, 4), 256>>>(feat);
    sup1_kernel<<<(NN * HH) / 256, 256>>>(Wc1);
    agg1_kernel<<<(SS * EE * 16) / 256, 256>>>(esrc, edst, edge_w);
    sup2_kernel<<<NN / 64, 256>>>(W2, Wc2);
    agg2_kernel<<<(SS * EE * 8) / 256, 256>>>(esrc, edst, edge_w);
    clf_kernel<<<NN / 256, 256>>>(Wclf, bclf, out);
}